// round 10
// baseline (speedup 1.0000x reference)
#include <cuda_runtime.h>
#include <cuda_fp16.h>
#include <cstdint>

// Problem constants
#define BATCH   32768
#define TSTEPS  30
#define HID     384
#define KTOT    400     // 8 rowvec + 384 hidden + 8 zero pad
#define NKB     25      // K blocks of 16
#define NMAIN   144     // fragments per kb (24 ub * 6: gate3 x uh2)
#define MROWS   64      // batch rows per CTA
#define NTH     256     // 8 warps; 2 CTAs/SM
#define LDHH    408     // sA row stride in halfs (816B rows: LDSM conflict-free)
#define WLDH    204     // row stride in 32-bit words
#define AHSZ    (MROWS*LDHH)   // halfs per A buffer
#define DECLD   66      // sDec row stride in halfs

// -------- static device scratch (fp16 fragment tables) --------
__device__ uint2 g_Bh[NKB * NMAIN * 32];    // main GEMM B (r,z,n_h)
__device__ uint2 g_Bnih[48 * 32];           // n_i B: kb=0 only, 48 usb
__device__ uint2 g_Wd1h[24 * 8 * 32];       // decode B

__device__ __forceinline__ unsigned packh2(float a, float b) {
    __half2 h = __floats2half2_rn(a, b);
    return *reinterpret_cast<unsigned*>(&h);
}
__device__ __forceinline__ float sigf(float x) { return 1.0f / (1.0f + __expf(-x)); }
__device__ __forceinline__ float tanhf_fast(float x) {
    return 2.0f / (1.0f + __expf(-2.0f * x)) - 1.0f;
}

__device__ __forceinline__ void mma_f16(float* c, const unsigned* a, unsigned b0, unsigned b1) {
    asm volatile(
        "mma.sync.aligned.m16n8k16.row.col.f32.f16.f16.f32 "
        "{%0,%1,%2,%3}, {%4,%5,%6,%7}, {%8,%9}, {%0,%1,%2,%3};\n"
        : "+f"(c[0]), "+f"(c[1]), "+f"(c[2]), "+f"(c[3])
        : "r"(a[0]), "r"(a[1]), "r"(a[2]), "r"(a[3]), "r"(b0), "r"(b1));
}
__device__ __forceinline__ void ldsm_x4(unsigned* a, unsigned saddr) {
    asm volatile(
        "ldmatrix.sync.aligned.m8n8.x4.shared.b16 {%0,%1,%2,%3}, [%4];\n"
        : "=r"(a[0]), "=r"(a[1]), "=r"(a[2]), "=r"(a[3]) : "r"(saddr));
}

// -------- prep value helpers (identical math) --------
__device__ float bval_main(int k, int ub, int colub,
                           const float* Wih, const float* bih,
                           const float* Whh, const float* bhh,
                           const float* Wp, const float* bp,
                           const float* Ws, const float* bs) {
    if (k >= 392) return 0.0f;               // K pad
    int gate = colub >> 4;                   // 0=r,1=z,2=n_h
    int u = ub * 16 + (colub & 15);
    if (k >= 8) {
        int kk = k - 8;
        int grow = (gate == 2 ? 768 : gate * 384) + u;
        return Whh[grow * HID + kk];
    }
    if (gate == 2) return (k == 0) ? bhh[768 + u] : 0.0f;   // n_h: bias only
    int grow = gate * 384 + u;
    const float* wr = Wih + grow * 128;
    float s = 0.0f;
    if (k == 0) {
        s = bih[grow] + bhh[grow];
        for (int m = 0; m < 128; m++) s += bs[m] * wr[m];
    } else if (k == 1) {
        for (int m = 0; m < 128; m++) s += bp[m] * wr[m];
    } else if (k < 5) {
        int d = k - 2;
        for (int m = 0; m < 128; m++) s += Ws[m * 3 + d] * wr[m];
    } else {
        int d = k - 5;
        for (int m = 0; m < 128; m++) s += Wp[m * 3 + d] * wr[m];
    }
    return s;
}

__device__ float bval_ni(int k, int u,
                         const float* Wih, const float* bih,
                         const float* Wp, const float* bp,
                         const float* Ws, const float* bs) {
    if (k >= 8) return 0.0f;                 // n_i: rowvec only
    int grow = 768 + u;
    const float* wr = Wih + grow * 128;
    float s = 0.0f;
    if (k == 0) {
        s = bih[grow];
        for (int m = 0; m < 128; m++) s += bs[m] * wr[m];
    } else if (k == 1) {
        for (int m = 0; m < 128; m++) s += bp[m] * wr[m];
    } else if (k < 5) {
        int d = k - 2;
        for (int m = 0; m < 128; m++) s += Ws[m * 3 + d] * wr[m];
    } else {
        int d = k - 5;
        for (int m = 0; m < 128; m++) s += Wp[m * 3 + d] * wr[m];
    }
    return s;
}

__global__ void prep_kernel(const float* __restrict__ W_ih, const float* __restrict__ b_ih,
                            const float* __restrict__ W_hh, const float* __restrict__ b_hh,
                            const float* __restrict__ Wp,  const float* __restrict__ bp,
                            const float* __restrict__ Ws,  const float* __restrict__ bs,
                            const float* __restrict__ Wd1) {
    int gid = blockIdx.x * blockDim.x + threadIdx.x;
    const int nMain = NKB * NMAIN;
    const int total = (nMain + 48 + 24 * 8) * 32;
    for (int w = gid; w < total; w += gridDim.x * blockDim.x) {
        int fid = w >> 5, lane = w & 31;
        int tig = lane & 3, g = lane >> 2;
        if (fid < nMain) {
            int kb = fid / NMAIN, rem = fid - kb * NMAIN;
            int ub = rem / 6, n8l = rem - ub * 6;
            int colub = n8l * 8 + g;
            int k0 = kb * 16;
            float v00 = bval_main(k0 + 2 * tig,     ub, colub, W_ih, b_ih, W_hh, b_hh, Wp, bp, Ws, bs);
            float v01 = bval_main(k0 + 2 * tig + 1, ub, colub, W_ih, b_ih, W_hh, b_hh, Wp, bp, Ws, bs);
            float v10 = bval_main(k0 + 2 * tig + 8, ub, colub, W_ih, b_ih, W_hh, b_hh, Wp, bp, Ws, bs);
            float v11 = bval_main(k0 + 2 * tig + 9, ub, colub, W_ih, b_ih, W_hh, b_hh, Wp, bp, Ws, bs);
            g_Bh[fid * 32 + lane] = make_uint2(packh2(v00, v01), packh2(v10, v11));
        } else if (fid < nMain + 48) {
            int usb = fid - nMain;
            int u = usb * 8 + g;
            float v00 = bval_ni(2 * tig,     u, W_ih, b_ih, Wp, bp, Ws, bs);
            float v01 = bval_ni(2 * tig + 1, u, W_ih, b_ih, Wp, bp, Ws, bs);
            g_Bnih[usb * 32 + lane] = make_uint2(packh2(v00, v01), packh2(0.0f, 0.0f));
        } else {
            int f = fid - nMain - 48;        // 24 kd * 8 c8
            int kd = f >> 3, c8 = f & 7;
            int n = c8 * 8 + g;
            int k = kd * 16 + 2 * tig;
            float v00 = Wd1[n * HID + k];
            float v01 = Wd1[n * HID + k + 1];
            float v10 = Wd1[n * HID + k + 8];
            float v11 = Wd1[n * HID + k + 9];
            g_Wd1h[f * 32 + lane] = make_uint2(packh2(v00, v01), packh2(v10, v11));
        }
    }
}

// -------- main fused GRU rollout: fp16 MMA + ldmatrix, 8 warps, 2 CTAs/SM --------
__global__ __launch_bounds__(NTH, 2)
void gru_kernel(const float* __restrict__ init_hidden,
                const float* __restrict__ plan,
                const float* __restrict__ gate,
                const float* __restrict__ init_state,
                const float* __restrict__ bd1,
                const float* __restrict__ Wd2,
                const float* __restrict__ bd2,
                float* __restrict__ out) {
    extern __shared__ char smraw[];
    __half* sA0h  = (__half*)smraw;                 // [64][408] ping
    __half* sA1h  = sA0h + AHSZ;                    // pong
    __half* sDech = sA1h + AHSZ;                    // [64][66]
    float*  sStat = (float*)(sDech + 64 * DECLD);   // [192]
    float*  sGate = sStat + 192;                    // [64]
    float*  sbd1  = sGate + 64;                     // [64]
    float*  sWd2  = sbd1 + 64;                      // [192]
    float*  sbd2  = sWd2 + 192;                     // [4]

    const int tid  = threadIdx.x;
    const int warp = tid >> 5;
    const int lane = tid & 31;
    const int g8   = lane >> 2;
    const int tig  = lane & 3;
    const int row0 = blockIdx.x * MROWS;

    // ldmatrix per-lane row/col pattern (x4: lanes 0-15 rows, lanes 16-31 col+8)
    const int lrow = lane & 15;
    const int lcolb = (lane >> 4) << 4;     // byte offset 0 or 16
    const unsigned aBase0 = (unsigned)__cvta_generic_to_shared(sA0h);
    const unsigned aBase1 = (unsigned)__cvta_generic_to_shared(sA1h);
    unsigned rowOff[4];
    #pragma unroll
    for (int mf = 0; mf < 4; mf++)
        rowOff[mf] = (unsigned)(((mf * 16 + lrow) * LDHH) * 2 + lcolb);

    // ---- init ----
    for (int i = tid; i < MROWS * HID; i += NTH) {
        int r = i / HID, u = i - r * HID;
        sA0h[r * LDHH + 8 + u] = __float2half_rn(init_hidden[(size_t)row0 * HID + i]);
    }
    for (int i = tid; i < MROWS * 8; i += NTH) {   // zero K-pad cols, both buffers
        int r = i >> 3, c = i & 7;
        sA0h[r * LDHH + 392 + c] = __ushort_as_half(0);
        sA1h[r * LDHH + 392 + c] = __ushort_as_half(0);
    }
    if (tid < 192) { sStat[tid] = init_state[(size_t)row0 * 3 + tid]; sWd2[tid] = Wd2[tid]; }
    if (tid < 64)  { sGate[tid] = gate[row0 + tid]; sbd1[tid] = bd1[tid]; }
    if (tid < 3)   sbd2[tid] = bd2[tid];
    __syncthreads();

    for (int t = 0; t < TSTEPS; t++) {
        __half* Acur = (t & 1) ? sA1h : sA0h;
        __half* Anxt = (t & 1) ? sA0h : sA1h;
        const unsigned* Aw = (const unsigned*)Acur;
        const unsigned aCur = (t & 1) ? aBase1 : aBase0;
        const unsigned aNxt = (t & 1) ? aBase0 : aBase1;

        // ---- phase 0: rowvec = [1, g, S0..2, g*P0..2] into cols 0..7 ----
        {
            int r = tid >> 2, c2 = tid & 3;
            float g0 = sGate[r];
            float v0, v1;
            if (c2 == 0)      { v0 = 1.0f;          v1 = g0; }
            else if (c2 == 1) { v0 = sStat[r * 3];  v1 = sStat[r * 3 + 1]; }
            else if (c2 == 2) { v0 = sStat[r * 3 + 2];
                                v1 = g0 * plan[((size_t)(row0 + r) * TSTEPS + t) * 3 + 0]; }
            else              { v0 = g0 * plan[((size_t)(row0 + r) * TSTEPS + t) * 3 + 1];
                                v1 = g0 * plan[((size_t)(row0 + r) * TSTEPS + t) * 3 + 2]; }
            ((unsigned*)Acur)[r * WLDH + c2] = packh2(v0, v1);
        }
        __syncthreads();

        // ---- phase 1: GEMM (64 x 1152 dense + n_i micro) + gate math ----
        for (int task = 0; task < 6; task++) {
            const int usb = warp + 8 * task;       // 8-col sub-block 0..47
            const int ub  = usb >> 1;
            const int uh  = usb & 1;

            float acc[48];                         // [mf=4][gate=3] x 4
            float accN[16];                        // [mf=4] x 4 (n_i)
            #pragma unroll
            for (int i = 0; i < 48; i++) acc[i] = 0.0f;
            #pragma unroll
            for (int i = 0; i < 16; i++) accN[i] = 0.0f;

            const uint2* Bbase = g_Bh + (size_t)(ub * 6 + uh) * 32 + lane;
            uint2 bb[2][3];
            #pragma unroll
            for (int gi = 0; gi < 3; gi++) bb[0][gi] = Bbase[gi * 64];
            uint2 bni = g_Bnih[usb * 32 + lane];

            #pragma unroll 5
            for (int kb = 0; kb < NKB; kb++) {
                const int cur = kb & 1;
                if (kb < NKB - 1) {
                    const uint2* Bn = Bbase + (size_t)(kb + 1) * (NMAIN * 32);
                    #pragma unroll
                    for (int gi = 0; gi < 3; gi++) bb[cur ^ 1][gi] = Bn[gi * 64];
                }
                // A fragments: 4 x ldmatrix.x4 (conflict-free)
                unsigned a[16];
                #pragma unroll
                for (int mf = 0; mf < 4; mf++)
                    ldsm_x4(&a[mf * 4], aCur + rowOff[mf] + kb * 32);
                if (kb == 0) {   // n_i: rowvec-only contribution
                    #pragma unroll
                    for (int mf = 0; mf < 4; mf++)
                        mma_f16(&accN[mf * 4], &a[mf * 4], bni.x, bni.y);
                }
                #pragma unroll
                for (int gi = 0; gi < 3; gi++) {
                    #pragma unroll
                    for (int mf = 0; mf < 4; mf++)
                        mma_f16(&acc[(mf * 3 + gi) * 4], &a[mf * 4], bb[cur][gi].x, bb[cur][gi].y);
                }
            }

            // gate math on fragments; write hidden as half2 pairs
            #pragma unroll
            for (int mf = 0; mf < 4; mf++)
            #pragma unroll
            for (int h = 0; h < 2; h++) {
                int row = mf * 16 + g8 + h * 8;
                int widx = row * WLDH + 4 + usb * 4 + tig;
                int e0 = 2 * h;
                __half2 hold2 = *(const __half2*)&Aw[widx];
                float2 holdf = __half22float2(hold2);
                float hn[2];
                #pragma unroll
                for (int q = 0; q < 2; q++) {
                    int e = e0 + q;
                    float rg = sigf(acc[(mf * 3 + 0) * 4 + e]);
                    float zg = sigf(acc[(mf * 3 + 1) * 4 + e]);
                    float nn = tanhf_fast(accN[mf * 4 + e] + rg * acc[(mf * 3 + 2) * 4 + e]);
                    float ho = (q == 0) ? holdf.x : holdf.y;
                    hn[q] = (1.0f - zg) * nn + zg * ho;
                }
                ((unsigned*)Anxt)[widx] = packh2(hn[0], hn[1]);
            }
        }
        __syncthreads();

        // ---- phase 2: decode layer1 (64x64, K=384) fp16 MMA + ldmatrix ----
        {
            float dacc[16];
            #pragma unroll
            for (int i = 0; i < 16; i++) dacc[i] = 0.0f;

            uint2 bv = g_Wd1h[warp * 32 + lane];
            #pragma unroll 2
            for (int kd = 0; kd < 24; kd++) {
                uint2 bcur = bv;
                if (kd < 23) bv = g_Wd1h[((kd + 1) * 8 + warp) * 32 + lane];
                unsigned a[16];
                #pragma unroll
                for (int mf = 0; mf < 4; mf++)
                    ldsm_x4(&a[mf * 4], aNxt + rowOff[mf] + 16 + kd * 32);
                #pragma unroll
                for (int mf = 0; mf < 4; mf++)
                    mma_f16(&dacc[mf * 4], &a[mf * 4], bcur.x, bcur.y);
            }
            #pragma unroll
            for (int mf = 0; mf < 4; mf++)
            #pragma unroll
            for (int h = 0; h < 2; h++) {
                int row = mf * 16 + g8 + h * 8;
                int col = warp * 8 + tig * 2;
                float v0 = dacc[mf * 4 + 2 * h]     + sbd1[col];
                float v1 = dacc[mf * 4 + 2 * h + 1] + sbd1[col + 1];
                v0 = v0 > 0.0f ? v0 : (__expf(v0) - 1.0f);    // ELU
                v1 = v1 > 0.0f ? v1 : (__expf(v1) - 1.0f);
                *(unsigned*)(sDech + row * DECLD + col) = packh2(v0, v1);
            }
        }
        __syncthreads();

        // ---- phase 3: decode layer2 + state update + output ----
        if (tid < 192) {
            int r = tid / 3, c = tid - r * 3;
            float acc = sbd2[c];
            const float* w2 = sWd2 + c * 64;
            const __half2* dp = (const __half2*)(sDech + r * DECLD);
            #pragma unroll 8
            for (int k2 = 0; k2 < 32; k2++) {
                float2 f = __half22float2(dp[k2]);
                acc += f.x * w2[2 * k2] + f.y * w2[2 * k2 + 1];
            }
            float ns = sStat[tid] + acc;
            sStat[tid] = ns;
            out[((size_t)(row0 + r) * TSTEPS + t) * 3 + c] = ns;
        }
        __syncthreads();
    }
}

// -------- launch --------
extern "C" void kernel_launch(void* const* d_in, const int* in_sizes, int n_in,
                              void* d_out, int out_size) {
    const float* init_hidden = (const float*)d_in[0];
    const float* plan        = (const float*)d_in[1];
    const float* gatep       = (const float*)d_in[2];
    const float* init_state  = (const float*)d_in[3];
    const float* Wp   = (const float*)d_in[4];
    const float* bp   = (const float*)d_in[5];
    const float* Ws   = (const float*)d_in[6];
    const float* bs   = (const float*)d_in[7];
    const float* W_ih = (const float*)d_in[8];
    const float* b_ih = (const float*)d_in[9];
    const float* W_hh = (const float*)d_in[10];
    const float* b_hh = (const float*)d_in[11];
    const float* Wd1  = (const float*)d_in[12];
    const float* bd1  = (const float*)d_in[13];
    const float* Wd2  = (const float*)d_in[14];
    const float* bd2  = (const float*)d_in[15];
    float* out = (float*)d_out;

    prep_kernel<<<480, 256>>>(W_ih, b_ih, W_hh, b_hh, Wp, bp, Ws, bs, Wd1);

    const size_t smem_bytes = (size_t)(2 * AHSZ + 64 * DECLD) * sizeof(__half)
                            + (192 + 64 + 64 + 192 + 4) * sizeof(float);
    cudaFuncSetAttribute(gru_kernel, cudaFuncAttributeMaxDynamicSharedMemorySize,
                         (int)smem_bytes);

    gru_kernel<<<BATCH / MROWS, NTH, smem_bytes>>>(
        init_hidden, plan, gatep, init_state, bd1, Wd2, bd2, out);
}

// round 12
// speedup vs baseline: 1.4219x; 1.4219x over previous
#include <cuda_runtime.h>
#include <cuda_fp16.h>
#include <cstdint>

// Problem constants
#define BATCH   32768
#define TSTEPS  30
#define HID     384
#define KTOT    400     // 8 rowvec + 384 hidden + 8 zero pad
#define NKB     25      // K blocks of 16 (main GEMM)
#define NKD     25      // decode K blocks (block-aligned, zero-padded)
#define NMAIN   144     // fragments per kb (24 ub * 6: gate3 x uh2)
#define MROWS   64      // batch rows per CTA
#define NTH     256     // 8 warps; 2 CTAs/SM
#define LDHH    400     // sA row stride in halfs
#define WLDH    200     // row stride in 32-bit words (200 % 32 == 8 -> LDS.64 conflict-free)
#define AHSZ    (MROWS*LDHH)   // halfs per A buffer
#define DECLD   66      // sDec row stride in halfs

// A row layout: col c -> block bk=c>>4, pair p=(c&15)>>1, word = bk*8 + (p&3)*2 + (p>>2).
// Word kb*8+2t   holds cols (16kb+2t,   16kb+2t+1)   -> a0/a1 of fragment kb
// Word kb*8+2t+1 holds cols (16kb+8+2t, 16kb+9+2t)   -> a2/a3 of fragment kb
// => one LDS.64 per row-half per fragment.

// -------- static device scratch (fp16 fragment tables) --------
__device__ uint2 g_Bh[NKB * NMAIN * 32];    // main GEMM B (r,z,n_h)
__device__ uint2 g_Bnih[48 * 32];           // n_i B: kb=0 only, 48 usb
__device__ uint2 g_Wd1h[NKD * 8 * 32];      // decode B (block-aligned, padded)

__device__ __forceinline__ unsigned packh2(float a, float b) {
    __half2 h = __floats2half2_rn(a, b);
    return *reinterpret_cast<unsigned*>(&h);
}
__device__ __forceinline__ float sigf(float x) { return 1.0f / (1.0f + __expf(-x)); }
__device__ __forceinline__ float tanhf_fast(float x) {
    return 2.0f / (1.0f + __expf(-2.0f * x)) - 1.0f;
}
__device__ __forceinline__ int wordof(int c) {      // init-path only
    int bk = c >> 4, p = (c & 15) >> 1;
    return bk * 8 + ((p & 3) << 1) + (p >> 2);
}

__device__ __forceinline__ void mma_f16(float* c, const unsigned* a, unsigned b0, unsigned b1) {
    asm volatile(
        "mma.sync.aligned.m16n8k16.row.col.f32.f16.f16.f32 "
        "{%0,%1,%2,%3}, {%4,%5,%6,%7}, {%8,%9}, {%0,%1,%2,%3};\n"
        : "+f"(c[0]), "+f"(c[1]), "+f"(c[2]), "+f"(c[3])
        : "r"(a[0]), "r"(a[1]), "r"(a[2]), "r"(a[3]), "r"(b0), "r"(b1));
}

// -------- prep value helpers (identical math to rounds 4-11) --------
__device__ float bval_main(int k, int ub, int colub,
                           const float* Wih, const float* bih,
                           const float* Whh, const float* bhh,
                           const float* Wp, const float* bp,
                           const float* Ws, const float* bs) {
    if (k >= 392) return 0.0f;               // K pad
    int gate = colub >> 4;                   // 0=r,1=z,2=n_h
    int u = ub * 16 + (colub & 15);
    if (k >= 8) {
        int kk = k - 8;
        int grow = (gate == 2 ? 768 : gate * 384) + u;
        return Whh[grow * HID + kk];
    }
    if (gate == 2) return (k == 0) ? bhh[768 + u] : 0.0f;   // n_h: bias only
    int grow = gate * 384 + u;
    const float* wr = Wih + grow * 128;
    float s = 0.0f;
    if (k == 0) {
        s = bih[grow] + bhh[grow];
        for (int m = 0; m < 128; m++) s += bs[m] * wr[m];
    } else if (k == 1) {
        for (int m = 0; m < 128; m++) s += bp[m] * wr[m];
    } else if (k < 5) {
        int d = k - 2;
        for (int m = 0; m < 128; m++) s += Ws[m * 3 + d] * wr[m];
    } else {
        int d = k - 5;
        for (int m = 0; m < 128; m++) s += Wp[m * 3 + d] * wr[m];
    }
    return s;
}

__device__ float bval_ni(int k, int u,
                         const float* Wih, const float* bih,
                         const float* Wp, const float* bp,
                         const float* Ws, const float* bs) {
    if (k >= 8) return 0.0f;                 // n_i: rowvec only
    int grow = 768 + u;
    const float* wr = Wih + grow * 128;
    float s = 0.0f;
    if (k == 0) {
        s = bih[grow];
        for (int m = 0; m < 128; m++) s += bs[m] * wr[m];
    } else if (k == 1) {
        for (int m = 0; m < 128; m++) s += bp[m] * wr[m];
    } else if (k < 5) {
        int d = k - 2;
        for (int m = 0; m < 128; m++) s += Ws[m * 3 + d] * wr[m];
    } else {
        int d = k - 5;
        for (int m = 0; m < 128; m++) s += Wp[m * 3 + d] * wr[m];
    }
    return s;
}

__global__ void prep_kernel(const float* __restrict__ W_ih, const float* __restrict__ b_ih,
                            const float* __restrict__ W_hh, const float* __restrict__ b_hh,
                            const float* __restrict__ Wp,  const float* __restrict__ bp,
                            const float* __restrict__ Ws,  const float* __restrict__ bs,
                            const float* __restrict__ Wd1) {
    int gid = blockIdx.x * blockDim.x + threadIdx.x;
    const int nMain = NKB * NMAIN;
    const int total = (nMain + 48 + NKD * 8) * 32;
    for (int w = gid; w < total; w += gridDim.x * blockDim.x) {
        int fid = w >> 5, lane = w & 31;
        int tig = lane & 3, g = lane >> 2;
        if (fid < nMain) {
            int kb = fid / NMAIN, rem = fid - kb * NMAIN;
            int ub = rem / 6, n8l = rem - ub * 6;
            int colub = n8l * 8 + g;
            int k0 = kb * 16;
            float v00 = bval_main(k0 + 2 * tig,     ub, colub, W_ih, b_ih, W_hh, b_hh, Wp, bp, Ws, bs);
            float v01 = bval_main(k0 + 2 * tig + 1, ub, colub, W_ih, b_ih, W_hh, b_hh, Wp, bp, Ws, bs);
            float v10 = bval_main(k0 + 2 * tig + 8, ub, colub, W_ih, b_ih, W_hh, b_hh, Wp, bp, Ws, bs);
            float v11 = bval_main(k0 + 2 * tig + 9, ub, colub, W_ih, b_ih, W_hh, b_hh, Wp, bp, Ws, bs);
            g_Bh[fid * 32 + lane] = make_uint2(packh2(v00, v01), packh2(v10, v11));
        } else if (fid < nMain + 48) {
            int usb = fid - nMain;
            int u = usb * 8 + g;
            float v00 = bval_ni(2 * tig,     u, W_ih, b_ih, Wp, bp, Ws, bs);
            float v01 = bval_ni(2 * tig + 1, u, W_ih, b_ih, Wp, bp, Ws, bs);
            g_Bnih[usb * 32 + lane] = make_uint2(packh2(v00, v01), packh2(0.0f, 0.0f));
        } else {
            int f = fid - nMain - 48;        // NKD kd * 8 c8  (global-col space, zero pad)
            int kd = f >> 3, c8 = f & 7;
            int n = c8 * 8 + g;
            int c0 = kd * 16 + 2 * tig;
            float v00 = (c0     >= 8 && c0     < 392) ? Wd1[n * HID + c0 - 8] : 0.0f;
            float v01 = (c0 + 1 >= 8 && c0 + 1 < 392) ? Wd1[n * HID + c0 - 7] : 0.0f;
            float v10 = (c0 + 8 >= 8 && c0 + 8 < 392) ? Wd1[n * HID + c0]     : 0.0f;
            float v11 = (c0 + 9 >= 8 && c0 + 9 < 392) ? Wd1[n * HID + c0 + 1] : 0.0f;
            g_Wd1h[f * 32 + lane] = make_uint2(packh2(v00, v01), packh2(v10, v11));
        }
    }
}

// -------- main fused GRU rollout: fp16 MMA, LDS.64 A loads, 2 CTAs/SM --------
__global__ __launch_bounds__(NTH, 2)
void gru_kernel(const float* __restrict__ init_hidden,
                const float* __restrict__ plan,
                const float* __restrict__ gate,
                const float* __restrict__ init_state,
                const float* __restrict__ bd1,
                const float* __restrict__ Wd2,
                const float* __restrict__ bd2,
                float* __restrict__ out) {
    extern __shared__ char smraw[];
    __half* sA0h  = (__half*)smraw;                 // [64][400] ping (interleaved words)
    __half* sA1h  = sA0h + AHSZ;                    // pong
    __half* sDech = sA1h + AHSZ;                    // [64][66]
    float*  sStat = (float*)(sDech + 64 * DECLD);   // [192]
    float*  sGate = sStat + 192;                    // [64]
    float*  sbd1  = sGate + 64;                     // [64]
    float*  sWd2  = sbd1 + 64;                      // [192]
    float*  sbd2  = sWd2 + 192;                     // [4]

    const int tid  = threadIdx.x;
    const int warp = tid >> 5;
    const int lane = tid & 31;
    const int g8   = lane >> 2;
    const int tig  = lane & 3;
    const int row0 = blockIdx.x * MROWS;

    // ---- init ----
    for (int i = tid; i < MROWS * HID; i += NTH) {
        int r = i / HID, u = i - r * HID;
        int c = 8 + u;
        sA0h[r * LDHH + wordof(c) * 2 + (c & 1)] =
            __float2half_rn(init_hidden[(size_t)row0 * HID + i]);
    }
    // zero rowvec cols 0..7 AND K-pad cols 392..399 in BOTH buffers.
    // (decode reads these columns with zero B weights; they must be finite.
    //  phase 0 overwrites Acur's rowvec every step before the GEMM.)
    for (int i = tid; i < MROWS * 16; i += NTH) {
        int r = i >> 4, j = i & 15;
        int c = (j < 8) ? j : (384 + j);           // 0..7 or 392..399
        int hidx = r * LDHH + wordof(c) * 2 + (c & 1);
        sA0h[hidx] = __ushort_as_half(0);
        sA1h[hidx] = __ushort_as_half(0);
    }
    if (tid < 192) { sStat[tid] = init_state[(size_t)row0 * 3 + tid]; sWd2[tid] = Wd2[tid]; }
    if (tid < 64)  { sGate[tid] = gate[row0 + tid]; sbd1[tid] = bd1[tid]; }
    if (tid < 3)   sbd2[tid] = bd2[tid];
    __syncthreads();

    for (int t = 0; t < TSTEPS; t++) {
        __half* Acur = (t & 1) ? sA1h : sA0h;
        __half* Anxt = (t & 1) ? sA0h : sA1h;
        const unsigned* Aw = (const unsigned*)Acur;
        const uint2* A2c = (const uint2*)Acur;          // uint2 index = word/2
        const uint2* A2n = (const uint2*)Anxt;

        // ---- phase 0: rowvec = [1, g, S0..2, g*P0..2] -> pairs 0..3 (words 0,2,4,6) ----
        {
            int r = tid >> 2, c2 = tid & 3;
            float g0 = sGate[r];
            float v0, v1;
            if (c2 == 0)      { v0 = 1.0f;          v1 = g0; }
            else if (c2 == 1) { v0 = sStat[r * 3];  v1 = sStat[r * 3 + 1]; }
            else if (c2 == 2) { v0 = sStat[r * 3 + 2];
                                v1 = g0 * plan[((size_t)(row0 + r) * TSTEPS + t) * 3 + 0]; }
            else              { v0 = g0 * plan[((size_t)(row0 + r) * TSTEPS + t) * 3 + 1];
                                v1 = g0 * plan[((size_t)(row0 + r) * TSTEPS + t) * 3 + 2]; }
            ((unsigned*)Acur)[r * WLDH + c2 * 2] = packh2(v0, v1);
        }
        __syncthreads();

        // ---- phase 1: GEMM (64 x 1152 dense + n_i micro) + gate math ----
        for (int task = 0; task < 6; task++) {
            const int usb = warp + 8 * task;       // 8-col sub-block 0..47
            const int ub  = usb >> 1;
            const int uh  = usb & 1;
            const int ewBase = ((usb + 1) >> 1) * 8 + ((usb & 1) ^ 1);  // epilogue word base

            float acc[48];                         // [mf=4][gate=3] x 4
            float accN[16];                        // [mf=4] x 4 (n_i)
            #pragma unroll
            for (int i = 0; i < 48; i++) acc[i] = 0.0f;
            #pragma unroll
            for (int i = 0; i < 16; i++) accN[i] = 0.0f;

            const uint2* Bbase = g_Bh + (size_t)(ub * 6 + uh) * 32 + lane;
            uint2 bb[2][3];
            #pragma unroll
            for (int gi = 0; gi < 3; gi++) bb[0][gi] = Bbase[gi * 64];
            uint2 bni = g_Bnih[usb * 32 + lane];

            #pragma unroll 5
            for (int kb = 0; kb < NKB; kb++) {
                const int cur = kb & 1;
                if (kb < NKB - 1) {
                    const uint2* Bn = Bbase + (size_t)(kb + 1) * (NMAIN * 32);
                    #pragma unroll
                    for (int gi = 0; gi < 3; gi++) bb[cur ^ 1][gi] = Bn[gi * 64];
                }
                // A fragments: 8 x LDS.64, conflict-free (WLDH%32==8)
                unsigned a[16];
                #pragma unroll
                for (int mf = 0; mf < 4; mf++) {
                    int r0 = mf * 16 + g8;
                    uint2 lo = A2c[r0 * 100 + kb * 4 + tig];
                    uint2 hi = A2c[(r0 + 8) * 100 + kb * 4 + tig];
                    a[mf * 4 + 0] = lo.x;
                    a[mf * 4 + 1] = hi.x;
                    a[mf * 4 + 2] = lo.y;
                    a[mf * 4 + 3] = hi.y;
                }
                if (kb == 0) {   // n_i: rowvec-only contribution
                    #pragma unroll
                    for (int mf = 0; mf < 4; mf++)
                        mma_f16(&accN[mf * 4], &a[mf * 4], bni.x, bni.y);
                }
                #pragma unroll
                for (int gi = 0; gi < 3; gi++) {
                    #pragma unroll
                    for (int mf = 0; mf < 4; mf++)
                        mma_f16(&acc[(mf * 3 + gi) * 4], &a[mf * 4], bb[cur][gi].x, bb[cur][gi].y);
                }
            }

            // gate math on fragments; write hidden as half2 pairs (affine word addr)
            #pragma unroll
            for (int mf = 0; mf < 4; mf++)
            #pragma unroll
            for (int h = 0; h < 2; h++) {
                int row = mf * 16 + g8 + h * 8;
                int widx = row * WLDH + ewBase + tig * 2;
                int e0 = 2 * h;
                __half2 hold2 = *(const __half2*)&Aw[widx];
                float2 holdf = __half22float2(hold2);
                float hn[2];
                #pragma unroll
                for (int q = 0; q < 2; q++) {
                    int e = e0 + q;
                    float rg = sigf(acc[(mf * 3 + 0) * 4 + e]);
                    float zg = sigf(acc[(mf * 3 + 1) * 4 + e]);
                    float nn = tanhf_fast(accN[mf * 4 + e] + rg * acc[(mf * 3 + 2) * 4 + e]);
                    float ho = (q == 0) ? holdf.x : holdf.y;
                    hn[q] = (1.0f - zg) * nn + zg * ho;
                }
                ((unsigned*)Anxt)[widx] = packh2(hn[0], hn[1]);
            }
        }
        __syncthreads();

        // ---- phase 2: decode layer1 (64x64) fp16 MMA, block-aligned K=400 ----
        {
            float dacc[16];
            #pragma unroll
            for (int i = 0; i < 16; i++) dacc[i] = 0.0f;

            uint2 bv = g_Wd1h[warp * 32 + lane];
            #pragma unroll 5
            for (int kd = 0; kd < NKD; kd++) {
                uint2 bcur = bv;
                if (kd < NKD - 1) bv = g_Wd1h[((kd + 1) * 8 + warp) * 32 + lane];
                unsigned a[16];
                #pragma unroll
                for (int mf = 0; mf < 4; mf++) {
                    int r0 = mf * 16 + g8;
                    uint2 lo = A2n[r0 * 100 + kd * 4 + tig];
                    uint2 hi = A2n[(r0 + 8) * 100 + kd * 4 + tig];
                    a[mf * 4 + 0] = lo.x;
                    a[mf * 4 + 1] = hi.x;
                    a[mf * 4 + 2] = lo.y;
                    a[mf * 4 + 3] = hi.y;
                }
                #pragma unroll
                for (int mf = 0; mf < 4; mf++)
                    mma_f16(&dacc[mf * 4], &a[mf * 4], bcur.x, bcur.y);
            }
            #pragma unroll
            for (int mf = 0; mf < 4; mf++)
            #pragma unroll
            for (int h = 0; h < 2; h++) {
                int row = mf * 16 + g8 + h * 8;
                int col = warp * 8 + tig * 2;
                float v0 = dacc[mf * 4 + 2 * h]     + sbd1[col];
                float v1 = dacc[mf * 4 + 2 * h + 1] + sbd1[col + 1];
                v0 = v0 > 0.0f ? v0 : (__expf(v0) - 1.0f);    // ELU
                v1 = v1 > 0.0f ? v1 : (__expf(v1) - 1.0f);
                *(unsigned*)(sDech + row * DECLD + col) = packh2(v0, v1);
            }
        }
        __syncthreads();

        // ---- phase 3: decode layer2 + state update + output ----
        if (tid < 192) {
            int r = tid / 3, c = tid - r * 3;
            float acc = sbd2[c];
            const float* w2 = sWd2 + c * 64;
            const __half2* dp = (const __half2*)(sDech + r * DECLD);
            #pragma unroll 8
            for (int k2 = 0; k2 < 32; k2++) {
                float2 f = __half22float2(dp[k2]);
                acc += f.x * w2[2 * k2] + f.y * w2[2 * k2 + 1];
            }
            float ns = sStat[tid] + acc;
            sStat[tid] = ns;
            out[((size_t)(row0 + r) * TSTEPS + t) * 3 + c] = ns;
        }
        __syncthreads();
    }
}

// -------- launch --------
extern "C" void kernel_launch(void* const* d_in, const int* in_sizes, int n_in,
                              void* d_out, int out_size) {
    const float* init_hidden = (const float*)d_in[0];
    const float* plan        = (const float*)d_in[1];
    const float* gatep       = (const float*)d_in[2];
    const float* init_state  = (const float*)d_in[3];
    const float* Wp   = (const float*)d_in[4];
    const float* bp   = (const float*)d_in[5];
    const float* Ws   = (const float*)d_in[6];
    const float* bs   = (const float*)d_in[7];
    const float* W_ih = (const float*)d_in[8];
    const float* b_ih = (const float*)d_in[9];
    const float* W_hh = (const float*)d_in[10];
    const float* b_hh = (const float*)d_in[11];
    const float* Wd1  = (const float*)d_in[12];
    const float* bd1  = (const float*)d_in[13];
    const float* Wd2  = (const float*)d_in[14];
    const float* bd2  = (const float*)d_in[15];
    float* out = (float*)d_out;

    prep_kernel<<<480, 256>>>(W_ih, b_ih, W_hh, b_hh, Wp, bp, Ws, bs, Wd1);

    const size_t smem_bytes = (size_t)(2 * AHSZ + 64 * DECLD) * sizeof(__half)
                            + (192 + 64 + 64 + 192 + 4) * sizeof(float);
    cudaFuncSetAttribute(gru_kernel, cudaFuncAttributeMaxDynamicSharedMemorySize,
                         (int)smem_bytes);

    gru_kernel<<<BATCH / MROWS, NTH, smem_bytes>>>(
        init_hidden, plan, gatep, init_state, bd1, Wd2, bd2, out);
}

// round 13
// speedup vs baseline: 2.7836x; 1.9577x over previous
#include <cuda_runtime.h>
#include <cuda_fp16.h>
#include <cstdint>

// Problem constants
#define BATCH   32768
#define TSTEPS  30
#define HID     384
#define KTOT    400     // 8 rowvec + 384 hidden + 8 zero pad
#define NKB     25      // K blocks of 16
#define NMAIN   144     // fragments per kb (24 ub * 6: gate3 x uh2)
#define MROWS   64      // batch rows per CTA
#define NTH     256     // 8 warps; 2 CTAs/SM
#define LDHH    408     // sA row stride in halfs
#define WLDH    204     // row stride in 32-bit words
#define AHSZ    (MROWS*LDHH)   // halfs per A buffer
#define DECLD   66      // sDec row stride in halfs

// -------- static device scratch (fp16 fragment tables) --------
__device__ uint2 g_Bh[NKB * NMAIN * 32];    // main GEMM B (r,z,n_h)
__device__ uint2 g_Bnih[48 * 32];           // n_i B: kb=0 only, 48 usb
__device__ uint2 g_Wd1h[24 * 8 * 32];       // decode B

__device__ __forceinline__ unsigned packh2(float a, float b) {
    __half2 h = __floats2half2_rn(a, b);    // .x = a (low half / even col)
    return *reinterpret_cast<unsigned*>(&h);
}
__device__ __forceinline__ float tanh_hw(float x) {
    float y; asm("tanh.approx.f32 %0, %1;" : "=f"(y) : "f"(x)); return y;
}
__device__ __forceinline__ float sigf(float x) {
    return fmaf(0.5f, tanh_hw(0.5f * x), 0.5f);
}

__device__ __forceinline__ void mma_f16(float* c, const unsigned* a, unsigned b0, unsigned b1) {
    asm volatile(
        "mma.sync.aligned.m16n8k16.row.col.f32.f16.f16.f32 "
        "{%0,%1,%2,%3}, {%4,%5,%6,%7}, {%8,%9}, {%0,%1,%2,%3};\n"
        : "+f"(c[0]), "+f"(c[1]), "+f"(c[2]), "+f"(c[3])
        : "r"(a[0]), "r"(a[1]), "r"(a[2]), "r"(a[3]), "r"(b0), "r"(b1));
}

// -------- prep value helpers (identical math) --------
__device__ float bval_main(int k, int ub, int colub,
                           const float* Wih, const float* bih,
                           const float* Whh, const float* bhh,
                           const float* Wp, const float* bp,
                           const float* Ws, const float* bs) {
    if (k >= 392) return 0.0f;               // K pad
    int gate = colub >> 4;                   // 0=r,1=z,2=n_h
    int u = ub * 16 + (colub & 15);
    if (k >= 8) {
        int kk = k - 8;
        int grow = (gate == 2 ? 768 : gate * 384) + u;
        return Whh[grow * HID + kk];
    }
    if (gate == 2) return (k == 0) ? bhh[768 + u] : 0.0f;   // n_h: bias only
    int grow = gate * 384 + u;
    const float* wr = Wih + grow * 128;
    float s = 0.0f;
    if (k == 0) {
        s = bih[grow] + bhh[grow];
        for (int m = 0; m < 128; m++) s += bs[m] * wr[m];
    } else if (k == 1) {
        for (int m = 0; m < 128; m++) s += bp[m] * wr[m];
    } else if (k < 5) {
        int d = k - 2;
        for (int m = 0; m < 128; m++) s += Ws[m * 3 + d] * wr[m];
    } else {
        int d = k - 5;
        for (int m = 0; m < 128; m++) s += Wp[m * 3 + d] * wr[m];
    }
    return s;
}

__device__ float bval_ni(int k, int u,
                         const float* Wih, const float* bih,
                         const float* Wp, const float* bp,
                         const float* Ws, const float* bs) {
    if (k >= 8) return 0.0f;                 // n_i: rowvec only
    int grow = 768 + u;
    const float* wr = Wih + grow * 128;
    float s = 0.0f;
    if (k == 0) {
        s = bih[grow];
        for (int m = 0; m < 128; m++) s += bs[m] * wr[m];
    } else if (k == 1) {
        for (int m = 0; m < 128; m++) s += bp[m] * wr[m];
    } else if (k < 5) {
        int d = k - 2;
        for (int m = 0; m < 128; m++) s += Ws[m * 3 + d] * wr[m];
    } else {
        int d = k - 5;
        for (int m = 0; m < 128; m++) s += Wp[m * 3 + d] * wr[m];
    }
    return s;
}

__global__ void prep_kernel(const float* __restrict__ W_ih, const float* __restrict__ b_ih,
                            const float* __restrict__ W_hh, const float* __restrict__ b_hh,
                            const float* __restrict__ Wp,  const float* __restrict__ bp,
                            const float* __restrict__ Ws,  const float* __restrict__ bs,
                            const float* __restrict__ Wd1) {
    int gid = blockIdx.x * blockDim.x + threadIdx.x;
    const int nMain = NKB * NMAIN;
    const int total = (nMain + 48 + 24 * 8) * 32;
    for (int w = gid; w < total; w += gridDim.x * blockDim.x) {
        int fid = w >> 5, lane = w & 31;
        int tig = lane & 3, g = lane >> 2;
        if (fid < nMain) {
            int kb = fid / NMAIN, rem = fid - kb * NMAIN;
            int ub = rem / 6, n8l = rem - ub * 6;
            int colub = n8l * 8 + g;
            int k0 = kb * 16;
            float v00 = bval_main(k0 + 2 * tig,     ub, colub, W_ih, b_ih, W_hh, b_hh, Wp, bp, Ws, bs);
            float v01 = bval_main(k0 + 2 * tig + 1, ub, colub, W_ih, b_ih, W_hh, b_hh, Wp, bp, Ws, bs);
            float v10 = bval_main(k0 + 2 * tig + 8, ub, colub, W_ih, b_ih, W_hh, b_hh, Wp, bp, Ws, bs);
            float v11 = bval_main(k0 + 2 * tig + 9, ub, colub, W_ih, b_ih, W_hh, b_hh, Wp, bp, Ws, bs);
            g_Bh[fid * 32 + lane] = make_uint2(packh2(v00, v01), packh2(v10, v11));
        } else if (fid < nMain + 48) {
            int usb = fid - nMain;
            int u = usb * 8 + g;
            float v00 = bval_ni(2 * tig,     u, W_ih, b_ih, Wp, bp, Ws, bs);
            float v01 = bval_ni(2 * tig + 1, u, W_ih, b_ih, Wp, bp, Ws, bs);
            g_Bnih[usb * 32 + lane] = make_uint2(packh2(v00, v01), packh2(0.0f, 0.0f));
        } else {
            int f = fid - nMain - 48;        // 24 kd * 8 c8
            int kd = f >> 3, c8 = f & 7;
            int n = c8 * 8 + g;
            int k = kd * 16 + 2 * tig;
            float v00 = Wd1[n * HID + k];
            float v01 = Wd1[n * HID + k + 1];
            float v10 = Wd1[n * HID + k + 8];
            float v11 = Wd1[n * HID + k + 9];
            g_Wd1h[f * 32 + lane] = make_uint2(packh2(v00, v01), packh2(v10, v11));
        }
    }
}

// -------- main fused GRU rollout: fp16 MMA, 8 warps, 2 CTAs/SM --------
__global__ __launch_bounds__(NTH, 2)
void gru_kernel(const float* __restrict__ init_hidden,
                const float* __restrict__ plan,
                const float* __restrict__ gate,
                const float* __restrict__ init_state,
                const float* __restrict__ bd1,
                const float* __restrict__ Wd2,
                const float* __restrict__ bd2,
                float* __restrict__ out) {
    extern __shared__ char smraw[];
    __half* sA0h  = (__half*)smraw;                 // [64][408] ping
    __half* sA1h  = sA0h + AHSZ;                    // pong
    __half* sDech = sA1h + AHSZ;                    // [64][66]
    float*  sStat = (float*)(sDech + 64 * DECLD);   // [192]
    float*  sGate = sStat + 192;                    // [64]
    float*  sbd1  = sGate + 64;                     // [64]
    float*  sWd2  = sbd1 + 64;                      // [192]
    float*  sbd2  = sWd2 + 192;                     // [4]

    const int tid  = threadIdx.x;
    const int warp = tid >> 5;
    const int lane = tid & 31;
    const int g8   = lane >> 2;
    const int tig  = lane & 3;
    const int row0 = blockIdx.x * MROWS;

    // ---- init ----
    for (int i = tid; i < MROWS * HID; i += NTH) {
        int r = i / HID, u = i - r * HID;
        sA0h[r * LDHH + 8 + u] = __float2half_rn(init_hidden[(size_t)row0 * HID + i]);
    }
    for (int i = tid; i < MROWS * 8; i += NTH) {   // zero K-pad cols, both buffers
        int r = i >> 3, c = i & 7;
        sA0h[r * LDHH + 392 + c] = __ushort_as_half(0);
        sA1h[r * LDHH + 392 + c] = __ushort_as_half(0);
    }
    if (tid < 192) { sStat[tid] = init_state[(size_t)row0 * 3 + tid]; sWd2[tid] = Wd2[tid]; }
    if (tid < 64)  { sGate[tid] = gate[row0 + tid]; sbd1[tid] = bd1[tid]; }
    if (tid < 3)   sbd2[tid] = bd2[tid];
    __syncthreads();

    for (int t = 0; t < TSTEPS; t++) {
        __half* Acur = (t & 1) ? sA1h : sA0h;
        __half* Anxt = (t & 1) ? sA0h : sA1h;
        const unsigned* Aw = (const unsigned*)Acur;

        // ---- phase 0: rowvec = [1, g, S0..2, g*P0..2] into cols 0..7 ----
        {
            int r = tid >> 2, c2 = tid & 3;
            float g0 = sGate[r];
            float v0, v1;
            if (c2 == 0)      { v0 = 1.0f;          v1 = g0; }
            else if (c2 == 1) { v0 = sStat[r * 3];  v1 = sStat[r * 3 + 1]; }
            else if (c2 == 2) { v0 = sStat[r * 3 + 2];
                                v1 = g0 * plan[((size_t)(row0 + r) * TSTEPS + t) * 3 + 0]; }
            else              { v0 = g0 * plan[((size_t)(row0 + r) * TSTEPS + t) * 3 + 1];
                                v1 = g0 * plan[((size_t)(row0 + r) * TSTEPS + t) * 3 + 2]; }
            ((unsigned*)Acur)[r * WLDH + c2] = packh2(v0, v1);
        }
        __syncthreads();

        // ---- phase 1: GEMM (64 x 1152 dense + n_i micro) + gate math ----
        for (int task = 0; task < 6; task++) {
            const int usb = warp + 8 * task;       // 8-col sub-block 0..47
            const int ub  = usb >> 1;
            const int uh  = usb & 1;

            float acc[48];                         // [mf=4][gate=3] x 4
            float accN[16];                        // [mf=4] x 4 (n_i)
            #pragma unroll
            for (int i = 0; i < 48; i++) acc[i] = 0.0f;
            #pragma unroll
            for (int i = 0; i < 16; i++) accN[i] = 0.0f;

            const uint2* Bbase = g_Bh + (size_t)(ub * 6 + uh) * 32 + lane;
            uint2 bb[2][3];
            #pragma unroll
            for (int gi = 0; gi < 3; gi++) bb[0][gi] = Bbase[gi * 64];
            uint2 bni = g_Bnih[usb * 32 + lane];

            #pragma unroll
            for (int kb = 0; kb < NKB; kb++) {
                const int cur = kb & 1;
                if (kb < NKB - 1) {
                    const uint2* Bn = Bbase + (size_t)(kb + 1) * (NMAIN * 32);
                    #pragma unroll
                    for (int gi = 0; gi < 3; gi++) bb[cur ^ 1][gi] = Bn[gi * 64];
                }
                // A fragments: 16 LDS.32 of half2, immediate offsets (full unroll)
                unsigned a[16];
                #pragma unroll
                for (int mf = 0; mf < 4; mf++) {
                    int r0 = mf * 16 + g8;
                    int wbase = kb * 8 + tig;
                    a[mf * 4 + 0] = Aw[r0 * WLDH + wbase];
                    a[mf * 4 + 1] = Aw[(r0 + 8) * WLDH + wbase];
                    a[mf * 4 + 2] = Aw[r0 * WLDH + wbase + 4];
                    a[mf * 4 + 3] = Aw[(r0 + 8) * WLDH + wbase + 4];
                }
                if (kb == 0) {   // n_i: rowvec-only contribution (static with full unroll)
                    #pragma unroll
                    for (int mf = 0; mf < 4; mf++)
                        mma_f16(&accN[mf * 4], &a[mf * 4], bni.x, bni.y);
                }
                #pragma unroll
                for (int gi = 0; gi < 3; gi++) {
                    #pragma unroll
                    for (int mf = 0; mf < 4; mf++)
                        mma_f16(&acc[(mf * 3 + gi) * 4], &a[mf * 4], bb[cur][gi].x, bb[cur][gi].y);
                }
            }

            // gate math on fragments (HW tanh); write hidden as half2 pairs
            #pragma unroll
            for (int mf = 0; mf < 4; mf++)
            #pragma unroll
            for (int h = 0; h < 2; h++) {
                int row = mf * 16 + g8 + h * 8;
                int widx = row * WLDH + 4 + usb * 4 + tig;
                int e0 = 2 * h;
                __half2 hold2 = *(const __half2*)&Aw[widx];
                float2 holdf = __half22float2(hold2);
                float hn[2];
                #pragma unroll
                for (int q = 0; q < 2; q++) {
                    int e = e0 + q;
                    float rg = sigf(acc[(mf * 3 + 0) * 4 + e]);
                    float zg = sigf(acc[(mf * 3 + 1) * 4 + e]);
                    float nn = tanh_hw(accN[mf * 4 + e] + rg * acc[(mf * 3 + 2) * 4 + e]);
                    float ho = (q == 0) ? holdf.x : holdf.y;
                    hn[q] = (1.0f - zg) * nn + zg * ho;
                }
                ((unsigned*)Anxt)[widx] = packh2(hn[0], hn[1]);
            }
        }
        __syncthreads();

        // ---- phase 2: decode layer1 (64x64, K=384) fp16 MMA ----
        {
            const unsigned* Anw = (const unsigned*)Anxt;
            float dacc[16];
            #pragma unroll
            for (int i = 0; i < 16; i++) dacc[i] = 0.0f;

            uint2 bv = g_Wd1h[warp * 32 + lane];
            #pragma unroll 2
            for (int kd = 0; kd < 24; kd++) {
                uint2 bcur = bv;
                if (kd < 23) bv = g_Wd1h[((kd + 1) * 8 + warp) * 32 + lane];
                unsigned a[16];
                #pragma unroll
                for (int mf = 0; mf < 4; mf++) {
                    int r0 = mf * 16 + g8;
                    int wbase = 4 + kd * 8 + tig;
                    a[mf * 4 + 0] = Anw[r0 * WLDH + wbase];
                    a[mf * 4 + 1] = Anw[(r0 + 8) * WLDH + wbase];
                    a[mf * 4 + 2] = Anw[r0 * WLDH + wbase + 4];
                    a[mf * 4 + 3] = Anw[(r0 + 8) * WLDH + wbase + 4];
                }
                #pragma unroll
                for (int mf = 0; mf < 4; mf++)
                    mma_f16(&dacc[mf * 4], &a[mf * 4], bcur.x, bcur.y);
            }
            #pragma unroll
            for (int mf = 0; mf < 4; mf++)
            #pragma unroll
            for (int h = 0; h < 2; h++) {
                int row = mf * 16 + g8 + h * 8;
                int col = warp * 8 + tig * 2;
                float v0 = dacc[mf * 4 + 2 * h]     + sbd1[col];
                float v1 = dacc[mf * 4 + 2 * h + 1] + sbd1[col + 1];
                v0 = v0 > 0.0f ? v0 : (__expf(v0) - 1.0f);    // ELU
                v1 = v1 > 0.0f ? v1 : (__expf(v1) - 1.0f);
                *(unsigned*)(sDech + row * DECLD + col) = packh2(v0, v1);
            }
        }
        __syncthreads();

        // ---- phase 3: decode layer2 + state update + output ----
        if (tid < 192) {
            int r = tid / 3, c = tid - r * 3;
            float acc = sbd2[c];
            const float* w2 = sWd2 + c * 64;
            const __half2* dp = (const __half2*)(sDech + r * DECLD);
            #pragma unroll 8
            for (int k2 = 0; k2 < 32; k2++) {
                float2 f = __half22float2(dp[k2]);
                acc += f.x * w2[2 * k2] + f.y * w2[2 * k2 + 1];
            }
            float ns = sStat[tid] + acc;
            sStat[tid] = ns;
            out[((size_t)(row0 + r) * TSTEPS + t) * 3 + c] = ns;
        }
        __syncthreads();
    }
}

// -------- launch --------
extern "C" void kernel_launch(void* const* d_in, const int* in_sizes, int n_in,
                              void* d_out, int out_size) {
    const float* init_hidden = (const float*)d_in[0];
    const float* plan        = (const float*)d_in[1];
    const float* gatep       = (const float*)d_in[2];
    const float* init_state  = (const float*)d_in[3];
    const float* Wp   = (const float*)d_in[4];
    const float* bp   = (const float*)d_in[5];
    const float* Ws   = (const float*)d_in[6];
    const float* bs   = (const float*)d_in[7];
    const float* W_ih = (const float*)d_in[8];
    const float* b_ih = (const float*)d_in[9];
    const float* W_hh = (const float*)d_in[10];
    const float* b_hh = (const float*)d_in[11];
    const float* Wd1  = (const float*)d_in[12];
    const float* bd1  = (const float*)d_in[13];
    const float* Wd2  = (const float*)d_in[14];
    const float* bd2  = (const float*)d_in[15];
    float* out = (float*)d_out;

    prep_kernel<<<480, 256>>>(W_ih, b_ih, W_hh, b_hh, Wp, bp, Ws, bs, Wd1);

    const size_t smem_bytes = (size_t)(2 * AHSZ + 64 * DECLD) * sizeof(__half)
                            + (192 + 64 + 64 + 192 + 4) * sizeof(float);
    cudaFuncSetAttribute(gru_kernel, cudaFuncAttributeMaxDynamicSharedMemorySize,
                         (int)smem_bytes);

    gru_kernel<<<BATCH / MROWS, NTH, smem_bytes>>>(
        init_hidden, plan, gatep, init_state, bd1, Wd2, bd2, out);
}

// round 14
// speedup vs baseline: 2.9716x; 1.0675x over previous
#include <cuda_runtime.h>
#include <cuda_fp16.h>
#include <cstdint>

// Problem constants
#define BATCH   32768
#define TSTEPS  30
#define HID     384
// K layout: cols 0..7 rowvec, 8..15 zero, 16..399 hidden  (kb0 = pure rowvec block)
#define NKB     25      // K blocks of 16
#define NMAIN   144     // fragments per kb (24 ub * 6: gate3 x uh2)
#define MROWS   64      // batch rows per CTA
#define NTH     256     // 8 warps; 2 CTAs/SM
#define LDHH    408     // sA row stride in halfs
#define WLDH    204     // row stride in 32-bit words
#define AHSZ    (MROWS*LDHH)
#define DECLD   66      // sDec row stride in halfs

// -------- static device scratch (fp16 fragment tables) --------
__device__ uint2 g_Bh[NKB * NMAIN * 32];    // main GEMM B (r,z,n_h)
__device__ uint2 g_Bnih[48 * 32];           // n_i B: kb=0 only, 48 usb
__device__ uint2 g_Wd1h[24 * 8 * 32];       // decode B (kd = main kb-1)

__device__ __forceinline__ unsigned packh2(float a, float b) {
    __half2 h = __floats2half2_rn(a, b);
    return *reinterpret_cast<unsigned*>(&h);
}
__device__ __forceinline__ float tanh_hw(float x) {
    float y; asm("tanh.approx.f32 %0, %1;" : "=f"(y) : "f"(x)); return y;
}
__device__ __forceinline__ float sigf(float x) {
    return fmaf(0.5f, tanh_hw(0.5f * x), 0.5f);
}

__device__ __forceinline__ void mma_f16(float* c, const unsigned* a, unsigned b0, unsigned b1) {
    asm volatile(
        "mma.sync.aligned.m16n8k16.row.col.f32.f16.f16.f32 "
        "{%0,%1,%2,%3}, {%4,%5,%6,%7}, {%8,%9}, {%0,%1,%2,%3};\n"
        : "+f"(c[0]), "+f"(c[1]), "+f"(c[2]), "+f"(c[3])
        : "r"(a[0]), "r"(a[1]), "r"(a[2]), "r"(a[3]), "r"(b0), "r"(b1));
}

// -------- prep value helpers --------
// K rows: k<8 rowvec coeffs, 8..15 zero, k>=16 -> W_hh[.., k-16]
__device__ float bval_main(int k, int ub, int colub,
                           const float* Wih, const float* bih,
                           const float* Whh, const float* bhh,
                           const float* Wp, const float* bp,
                           const float* Ws, const float* bs) {
    int gate = colub >> 4;                   // 0=r,1=z,2=n_h
    int u = ub * 16 + (colub & 15);
    if (k >= 16) {
        int grow = (gate == 2 ? 768 : gate * 384) + u;
        return Whh[grow * HID + (k - 16)];
    }
    if (gate == 2) return (k == 0) ? bhh[768 + u] : 0.0f;   // n_h: bias only
    if (k >= 8) return 0.0f;
    int grow = gate * 384 + u;
    const float* wr = Wih + grow * 128;
    float s = 0.0f;
    if (k == 0) {
        s = bih[grow] + bhh[grow];
        for (int m = 0; m < 128; m++) s += bs[m] * wr[m];
    } else if (k == 1) {
        for (int m = 0; m < 128; m++) s += bp[m] * wr[m];
    } else if (k < 5) {
        int d = k - 2;
        for (int m = 0; m < 128; m++) s += Ws[m * 3 + d] * wr[m];
    } else {
        int d = k - 5;
        for (int m = 0; m < 128; m++) s += Wp[m * 3 + d] * wr[m];
    }
    return s;
}

__device__ float bval_ni(int k, int u,
                         const float* Wih, const float* bih,
                         const float* Wp, const float* bp,
                         const float* Ws, const float* bs) {
    if (k >= 8) return 0.0f;                 // n_i: rowvec only
    int grow = 768 + u;
    const float* wr = Wih + grow * 128;
    float s = 0.0f;
    if (k == 0) {
        s = bih[grow];
        for (int m = 0; m < 128; m++) s += bs[m] * wr[m];
    } else if (k == 1) {
        for (int m = 0; m < 128; m++) s += bp[m] * wr[m];
    } else if (k < 5) {
        int d = k - 2;
        for (int m = 0; m < 128; m++) s += Ws[m * 3 + d] * wr[m];
    } else {
        int d = k - 5;
        for (int m = 0; m < 128; m++) s += Wp[m * 3 + d] * wr[m];
    }
    return s;
}

__global__ void prep_kernel(const float* __restrict__ W_ih, const float* __restrict__ b_ih,
                            const float* __restrict__ W_hh, const float* __restrict__ b_hh,
                            const float* __restrict__ Wp,  const float* __restrict__ bp,
                            const float* __restrict__ Ws,  const float* __restrict__ bs,
                            const float* __restrict__ Wd1) {
    int gid = blockIdx.x * blockDim.x + threadIdx.x;
    const int nMain = NKB * NMAIN;
    const int total = (nMain + 48 + 24 * 8) * 32;
    for (int w = gid; w < total; w += gridDim.x * blockDim.x) {
        int fid = w >> 5, lane = w & 31;
        int tig = lane & 3, g = lane >> 2;
        if (fid < nMain) {
            int kb = fid / NMAIN, rem = fid - kb * NMAIN;
            int ub = rem / 6, n8l = rem - ub * 6;
            int colub = n8l * 8 + g;
            int k0 = kb * 16;
            float v00 = bval_main(k0 + 2 * tig,     ub, colub, W_ih, b_ih, W_hh, b_hh, Wp, bp, Ws, bs);
            float v01 = bval_main(k0 + 2 * tig + 1, ub, colub, W_ih, b_ih, W_hh, b_hh, Wp, bp, Ws, bs);
            float v10 = bval_main(k0 + 2 * tig + 8, ub, colub, W_ih, b_ih, W_hh, b_hh, Wp, bp, Ws, bs);
            float v11 = bval_main(k0 + 2 * tig + 9, ub, colub, W_ih, b_ih, W_hh, b_hh, Wp, bp, Ws, bs);
            g_Bh[fid * 32 + lane] = make_uint2(packh2(v00, v01), packh2(v10, v11));
        } else if (fid < nMain + 48) {
            int usb = fid - nMain;
            int u = usb * 8 + g;
            float v00 = bval_ni(2 * tig,     u, W_ih, b_ih, Wp, bp, Ws, bs);
            float v01 = bval_ni(2 * tig + 1, u, W_ih, b_ih, Wp, bp, Ws, bs);
            g_Bnih[usb * 32 + lane] = make_uint2(packh2(v00, v01), packh2(0.0f, 0.0f));
        } else {
            int f = fid - nMain - 48;        // 24 kd * 8 c8 ; kd = main kb-1
            int kd = f >> 3, c8 = f & 7;
            int n = c8 * 8 + g;
            int k = kd * 16 + 2 * tig;
            float v00 = Wd1[n * HID + k];
            float v01 = Wd1[n * HID + k + 1];
            float v10 = Wd1[n * HID + k + 8];
            float v11 = Wd1[n * HID + k + 9];
            g_Wd1h[f * 32 + lane] = make_uint2(packh2(v00, v01), packh2(v10, v11));
        }
    }
}

// -------- main fused GRU rollout: fp16 MMA, fused decode, 2 CTAs/SM --------
__global__ __launch_bounds__(NTH, 2)
void gru_kernel(const float* __restrict__ init_hidden,
                const float* __restrict__ plan,
                const float* __restrict__ gate,
                const float* __restrict__ init_state,
                const float* __restrict__ bd1,
                const float* __restrict__ Wd2,
                const float* __restrict__ bd2,
                float* __restrict__ out) {
    extern __shared__ char smraw[];
    __half* sA0h  = (__half*)smraw;                 // [64][408] ping
    __half* sA1h  = sA0h + AHSZ;                    // pong
    __half* sDech = sA1h + AHSZ;                    // [64][66]
    float*  sbd1  = (float*)(sDech + 64 * DECLD);   // [64]
    float*  sWd2  = sbd1 + 64;                      // [192]
    float*  sbd2  = sWd2 + 192;                     // [4]

    const int tid  = threadIdx.x;
    const int warp = tid >> 5;
    const int lane = tid & 31;
    const int g8   = lane >> 2;
    const int tig  = lane & 3;
    const int row0 = blockIdx.x * MROWS;

    float st0 = 0.0f, st1 = 0.0f, st2 = 0.0f, gx = 0.0f;   // state lanes (tid<64)

    // ---- init ----
    for (int i = tid; i < MROWS * HID; i += NTH) {
        int r = i / HID, u = i - r * HID;
        sA0h[r * LDHH + 16 + u] = __float2half_rn(init_hidden[(size_t)row0 * HID + i]);
    }
    for (int i = tid; i < MROWS * 8; i += NTH) {   // zero cols 8..15, both buffers
        int r = i >> 3, c = i & 7;
        sA0h[r * LDHH + 8 + c] = __ushort_as_half(0);
        sA1h[r * LDHH + 8 + c] = __ushort_as_half(0);
    }
    if (tid < 64) {
        gx  = gate[row0 + tid];
        st0 = init_state[(size_t)(row0 + tid) * 3 + 0];
        st1 = init_state[(size_t)(row0 + tid) * 3 + 1];
        st2 = init_state[(size_t)(row0 + tid) * 3 + 2];
        const float* pp = plan + (size_t)(row0 + tid) * TSTEPS * 3;   // t=0
        unsigned w0 = packh2(1.0f, gx);
        ((unsigned*)sA0h)[tid * WLDH + 0] = w0;
        ((unsigned*)sA1h)[tid * WLDH + 0] = w0;
        ((unsigned*)sA0h)[tid * WLDH + 1] = packh2(st0, st1);
        ((unsigned*)sA0h)[tid * WLDH + 2] = packh2(st2, gx * pp[0]);
        ((unsigned*)sA0h)[tid * WLDH + 3] = packh2(gx * pp[1], gx * pp[2]);
        sbd1[tid] = bd1[tid];
    }
    if (tid < 192) sWd2[tid] = Wd2[tid];
    if (tid < 3)   sbd2[tid] = bd2[tid];
    __syncthreads();

    // A-fragment loader (word wbase = kb*8+tig -> cols 16kb+2tig..)
    auto load_afrag = [&](unsigned* a, const unsigned* Aw, int kb) {
        #pragma unroll
        for (int mf = 0; mf < 4; mf++) {
            int r0 = mf * 16 + g8;
            int wb = kb * 8 + tig;
            a[mf * 4 + 0] = Aw[r0 * WLDH + wb];
            a[mf * 4 + 1] = Aw[(r0 + 8) * WLDH + wb];
            a[mf * 4 + 2] = Aw[r0 * WLDH + wb + 4];
            a[mf * 4 + 3] = Aw[(r0 + 8) * WLDH + wb + 4];
        }
    };
    // GRU epilogue for one usb (acc complete)
    auto gru_epilogue = [&](int usb, const float* acc, const float* accN,
                            const unsigned* Aw, unsigned* AnxtW) {
        #pragma unroll
        for (int mf = 0; mf < 4; mf++)
        #pragma unroll
        for (int h = 0; h < 2; h++) {
            int row = mf * 16 + g8 + h * 8;
            int widx = row * WLDH + 8 + usb * 4 + tig;
            __half2 hold2 = *(const __half2*)&Aw[widx];
            float2 holdf = __half22float2(hold2);
            float hn[2];
            #pragma unroll
            for (int q = 0; q < 2; q++) {
                int e = 2 * h + q;
                float rg = sigf(acc[(mf * 3 + 0) * 4 + e]);
                float zg = sigf(acc[(mf * 3 + 1) * 4 + e]);
                float nn = tanh_hw(accN[mf * 4 + e] + rg * acc[(mf * 3 + 2) * 4 + e]);
                float ho = (q == 0) ? holdf.x : holdf.y;
                hn[q] = (1.0f - zg) * nn + zg * ho;
            }
            AnxtW[widx] = packh2(hn[0], hn[1]);
        }
    };
    // ELU + store decode layer1 result
    auto elu_store = [&](const float* dacc) {
        #pragma unroll
        for (int mf = 0; mf < 4; mf++)
        #pragma unroll
        for (int h = 0; h < 2; h++) {
            int row = mf * 16 + g8 + h * 8;
            int col = warp * 8 + tig * 2;
            float v0 = dacc[mf * 4 + 2 * h]     + sbd1[col];
            float v1 = dacc[mf * 4 + 2 * h + 1] + sbd1[col + 1];
            v0 = v0 > 0.0f ? v0 : (__expf(v0) - 1.0f);
            v1 = v1 > 0.0f ? v1 : (__expf(v1) - 1.0f);
            *(unsigned*)(sDech + row * DECLD + col) = packh2(v0, v1);
        }
    };
    // full task (kb0..24) — used at t=0 and for tasks 1..5
    auto full_task = [&](int usb, const unsigned* Aw, unsigned* AnxtW) {
        int ub = usb >> 1, uh = usb & 1;
        float acc[48], accN[16];
        #pragma unroll
        for (int i = 0; i < 48; i++) acc[i] = 0.0f;
        #pragma unroll
        for (int i = 0; i < 16; i++) accN[i] = 0.0f;
        const uint2* Bbase = g_Bh + (size_t)(ub * 6 + uh) * 32 + lane;
        uint2 bb[2][3];
        #pragma unroll
        for (int gi = 0; gi < 3; gi++) bb[0][gi] = Bbase[gi * 64];
        uint2 bni = g_Bnih[usb * 32 + lane];
        #pragma unroll
        for (int kb = 0; kb < NKB; kb++) {
            int cur = kb & 1;
            if (kb < NKB - 1) {
                const uint2* Bn = Bbase + (size_t)(kb + 1) * (NMAIN * 32);
                #pragma unroll
                for (int gi = 0; gi < 3; gi++) bb[cur ^ 1][gi] = Bn[gi * 64];
            }
            unsigned a[16];
            load_afrag(a, Aw, kb);
            if (kb == 0) {
                #pragma unroll
                for (int mf = 0; mf < 4; mf++)
                    mma_f16(&accN[mf * 4], &a[mf * 4], bni.x, bni.y);
            }
            #pragma unroll
            for (int gi = 0; gi < 3; gi++)
                #pragma unroll
                for (int mf = 0; mf < 4; mf++)
                    mma_f16(&acc[(mf * 3 + gi) * 4], &a[mf * 4], bb[cur][gi].x, bb[cur][gi].y);
        }
        gru_epilogue(usb, acc, accN, Aw, AnxtW);
    };
    // phase3: decode layer2, state update, output, rowvec write
    auto phase3 = [&](int tcur, unsigned* AcurW, float pl0, float pl1, float pl2, bool rowvec) {
        const __half2* dp = (const __half2*)(sDech + tid * DECLD);
        float a0 = sbd2[0], a1 = sbd2[1], a2 = sbd2[2];
        #pragma unroll 8
        for (int k2 = 0; k2 < 32; k2++) {
            float2 f = __half22float2(dp[k2]);
            a0 += f.x * sWd2[2 * k2]       + f.y * sWd2[2 * k2 + 1];
            a1 += f.x * sWd2[64 + 2 * k2]  + f.y * sWd2[64 + 2 * k2 + 1];
            a2 += f.x * sWd2[128 + 2 * k2] + f.y * sWd2[128 + 2 * k2 + 1];
        }
        st0 += a0; st1 += a1; st2 += a2;
        float* op = out + ((size_t)(row0 + tid) * TSTEPS + (tcur - 1)) * 3;
        op[0] = st0; op[1] = st1; op[2] = st2;
        if (rowvec) {
            AcurW[tid * WLDH + 1] = packh2(st0, st1);
            AcurW[tid * WLDH + 2] = packh2(st2, gx * pl0);
            AcurW[tid * WLDH + 3] = packh2(gx * pl1, gx * pl2);
        }
    };

    for (int t = 0; t < TSTEPS; t++) {
        __half* Acur = (t & 1) ? sA1h : sA0h;
        __half* Anxt = (t & 1) ? sA0h : sA1h;
        const unsigned* Aw = (const unsigned*)Acur;
        unsigned* AcurW = (unsigned*)Acur;
        unsigned* AnxtW = (unsigned*)Anxt;

        if (t == 0) {
            for (int task = 0; task < 6; task++)
                full_task(warp + 8 * task, Aw, AnxtW);
        } else {
            // prefetch plan(t) for rowvec
            float pl0 = 0.0f, pl1 = 0.0f, pl2 = 0.0f;
            if (tid < 64) {
                const float* pp = plan + ((size_t)(row0 + tid) * TSTEPS + t) * 3;
                pl0 = pp[0]; pl1 = pp[1]; pl2 = pp[2];
            }
            // ---- merged task0: main kb1..24 + decode(hidden t) ----
            const int usb = warp;
            const int ub = usb >> 1, uh = usb & 1;
            float acc[48], dacc[16];
            #pragma unroll
            for (int i = 0; i < 48; i++) acc[i] = 0.0f;
            #pragma unroll
            for (int i = 0; i < 16; i++) dacc[i] = 0.0f;
            const uint2* Bbase = g_Bh + (size_t)(ub * 6 + uh) * 32 + lane;
            uint2 bb[2][3];
            #pragma unroll
            for (int gi = 0; gi < 3; gi++)
                bb[1][gi] = Bbase[(size_t)(NMAIN * 32) + gi * 64];     // kb=1
            uint2 bd = g_Wd1h[warp * 32 + lane];                        // kd=0
            #pragma unroll
            for (int kb = 1; kb <= 24; kb++) {
                int cur = kb & 1;
                if (kb < 24) {
                    const uint2* Bn = Bbase + (size_t)(kb + 1) * (NMAIN * 32);
                    #pragma unroll
                    for (int gi = 0; gi < 3; gi++) bb[cur ^ 1][gi] = Bn[gi * 64];
                }
                uint2 bdc = bd;
                if (kb < 24) bd = g_Wd1h[(kb * 8 + warp) * 32 + lane];
                unsigned a[16];
                load_afrag(a, Aw, kb);
                #pragma unroll
                for (int mf = 0; mf < 4; mf++)
                    mma_f16(&dacc[mf * 4], &a[mf * 4], bdc.x, bdc.y);
                #pragma unroll
                for (int gi = 0; gi < 3; gi++)
                    #pragma unroll
                    for (int mf = 0; mf < 4; mf++)
                        mma_f16(&acc[(mf * 3 + gi) * 4], &a[mf * 4], bb[cur][gi].x, bb[cur][gi].y);
            }
            // prefetch kb0's B + n_i B across the barriers
            uint2 b0f[3];
            #pragma unroll
            for (int gi = 0; gi < 3; gi++) b0f[gi] = Bbase[gi * 64];
            uint2 bni = g_Bnih[usb * 32 + lane];

            elu_store(dacc);
            __syncthreads();
            if (tid < 64) phase3(t, AcurW, pl0, pl1, pl2, true);
            __syncthreads();

            // kb0 (rowvec) + n_i + epilogue for task0
            {
                float accN[16];
                #pragma unroll
                for (int i = 0; i < 16; i++) accN[i] = 0.0f;
                unsigned a[16];
                load_afrag(a, Aw, 0);
                #pragma unroll
                for (int mf = 0; mf < 4; mf++)
                    mma_f16(&accN[mf * 4], &a[mf * 4], bni.x, bni.y);
                #pragma unroll
                for (int gi = 0; gi < 3; gi++)
                    #pragma unroll
                    for (int mf = 0; mf < 4; mf++)
                        mma_f16(&acc[(mf * 3 + gi) * 4], &a[mf * 4], b0f[gi].x, b0f[gi].y);
                gru_epilogue(usb, acc, accN, Aw, AnxtW);
            }
            // tasks 1..5 full
            for (int task = 1; task < 6; task++)
                full_task(warp + 8 * task, Aw, AnxtW);
        }
        __syncthreads();
    }

    // ---- final decode of hidden(TSTEPS) -> out[TSTEPS-1] ----
    {
        const __half* Af = (TSTEPS & 1) ? sA1h : sA0h;
        const unsigned* Aw = (const unsigned*)Af;
        float dacc[16];
        #pragma unroll
        for (int i = 0; i < 16; i++) dacc[i] = 0.0f;
        uint2 bd = g_Wd1h[warp * 32 + lane];
        #pragma unroll
        for (int kb = 1; kb <= 24; kb++) {
            uint2 bdc = bd;
            if (kb < 24) bd = g_Wd1h[(kb * 8 + warp) * 32 + lane];
            unsigned a[16];
            load_afrag(a, Aw, kb);
            #pragma unroll
            for (int mf = 0; mf < 4; mf++)
                mma_f16(&dacc[mf * 4], &a[mf * 4], bdc.x, bdc.y);
        }
        elu_store(dacc);
        __syncthreads();
        if (tid < 64) phase3(TSTEPS, (unsigned*)Af, 0.0f, 0.0f, 0.0f, false);
    }
}

// -------- launch --------
extern "C" void kernel_launch(void* const* d_in, const int* in_sizes, int n_in,
                              void* d_out, int out_size) {
    const float* init_hidden = (const float*)d_in[0];
    const float* plan        = (const float*)d_in[1];
    const float* gatep       = (const float*)d_in[2];
    const float* init_state  = (const float*)d_in[3];
    const float* Wp   = (const float*)d_in[4];
    const float* bp   = (const float*)d_in[5];
    const float* Ws   = (const float*)d_in[6];
    const float* bs   = (const float*)d_in[7];
    const float* W_ih = (const float*)d_in[8];
    const float* b_ih = (const float*)d_in[9];
    const float* W_hh = (const float*)d_in[10];
    const float* b_hh = (const float*)d_in[11];
    const float* Wd1  = (const float*)d_in[12];
    const float* bd1  = (const float*)d_in[13];
    const float* Wd2  = (const float*)d_in[14];
    const float* bd2  = (const float*)d_in[15];
    float* out = (float*)d_out;

    prep_kernel<<<480, 256>>>(W_ih, b_ih, W_hh, b_hh, Wp, bp, Ws, bs, Wd1);

    const size_t smem_bytes = (size_t)(2 * AHSZ + 64 * DECLD) * sizeof(__half)
                            + (64 + 192 + 4) * sizeof(float);
    cudaFuncSetAttribute(gru_kernel, cudaFuncAttributeMaxDynamicSharedMemorySize,
                         (int)smem_bytes);

    gru_kernel<<<BATCH / MROWS, NTH, smem_bytes>>>(
        init_hidden, plan, gatep, init_state, bd1, Wd2, bd2, out);
}